// round 1
// baseline (speedup 1.0000x reference)
#include <cuda_runtime.h>
#include <cstdint>

#define HD   1024
#define LSEQ 512
#define LAB  122
#define G4   (4*HD)     // 4096
#define IN5  (5*HD)     // 5120
#define NCTA 128

// ---------------- scratch (static __device__, no allocs) ----------------
__device__ float    g_G[(size_t)LSEQ * G4];   // precomputed input gates + bias  (8 MB)
__device__ float    g_outs[(size_t)LSEQ * HD]; // h_t for all t (2 MB)
__device__ float    g_h[2][HD];               // double-buffered recurrent state
__device__ unsigned g_cnt;                    // grid barrier counter

// ---------------- reset (graph replays must start clean) ----------------
__global__ void reset_kernel() {
    int i = blockIdx.x * blockDim.x + threadIdx.x;
    if (i < 2 * HD) ((float*)g_h)[i] = 0.f;
    if (i == 0) g_cnt = 0u;
}

// ---------------- tf32 mma helpers ----------------
__device__ __forceinline__ float to_tf32(float v) {
    uint32_t u;
    asm("cvt.rna.tf32.f32 %0, %1;" : "=r"(u) : "f"(v));
    return __uint_as_float(u);
}

__device__ __forceinline__ void mma_tf32(float* d, const uint32_t* a, const uint32_t* b) {
    asm volatile(
        "mma.sync.aligned.m16n8k8.row.col.f32.tf32.tf32.f32 "
        "{%0,%1,%2,%3}, {%4,%5,%6,%7}, {%8,%9}, {%0,%1,%2,%3};\n"
        : "+f"(d[0]), "+f"(d[1]), "+f"(d[2]), "+f"(d[3])
        : "r"(a[0]), "r"(a[1]), "r"(a[2]), "r"(a[3]), "r"(b[0]), "r"(b[1]));
}

// ---------------- Phase 1: G = F @ W_x^T + (b_ih + b_hh) ----------------
// F[t][k] = k<2048 ? x[t][k] : hi[t][k-2048];  W_x[r][k] = W_ih[r][k] (row stride 5120)
// Tiles: BM=64 (t), BN=64 (r), BK=16. 4 warps (2x2 of 32x32). Double-buffered smem.
__global__ void __launch_bounds__(128) gemm_kernel(
    const float* __restrict__ x, const float* __restrict__ hi,
    const float* __restrict__ W_ih,
    const float* __restrict__ b_ih, const float* __restrict__ b_hh)
{
    __shared__ float sA[2][16][72];   // [k][m], pad 72 -> conflict-free frag loads
    __shared__ float sB[2][16][72];   // [k][n]

    const int tid  = threadIdx.x;
    const int warp = tid >> 5, lane = tid & 31;
    const int grp  = lane >> 2, q = lane & 3;
    const int wm   = warp & 1, wn = warp >> 1;
    const int tm0  = blockIdx.y * 64;     // t tile
    const int rn0  = blockIdx.x * 64;     // gate-row tile

    const int lkq  = tid & 3;             // which float4 of the 16-wide k slab
    const int lrow = tid >> 2;            // 0..31

    float acc[2][4][4];
    #pragma unroll
    for (int a = 0; a < 2; a++)
        #pragma unroll
        for (int b = 0; b < 4; b++)
            #pragma unroll
            for (int c = 0; c < 4; c++) acc[a][b][c] = 0.f;

    float4 va0, va1, vb0, vb1;

    // prologue load kt=0
    {
        int kg = lkq * 4;
        const float* srcA = (kg < 2048) ? (x + kg) : (hi + kg - 2048);
        va0 = *(const float4*)(srcA + (size_t)(tm0 + lrow)      * 2048);
        va1 = *(const float4*)(srcA + (size_t)(tm0 + lrow + 32) * 2048);
        vb0 = *(const float4*)(W_ih + (size_t)(rn0 + lrow)      * IN5 + kg);
        vb1 = *(const float4*)(W_ih + (size_t)(rn0 + lrow + 32) * IN5 + kg);
    }
    {
        float ta0[4] = {va0.x, va0.y, va0.z, va0.w};
        float ta1[4] = {va1.x, va1.y, va1.z, va1.w};
        float tb0[4] = {vb0.x, vb0.y, vb0.z, vb0.w};
        float tb1[4] = {vb1.x, vb1.y, vb1.z, vb1.w};
        #pragma unroll
        for (int i = 0; i < 4; i++) {
            sA[0][lkq*4+i][lrow]      = to_tf32(ta0[i]);
            sA[0][lkq*4+i][lrow + 32] = to_tf32(ta1[i]);
            sB[0][lkq*4+i][lrow]      = to_tf32(tb0[i]);
            sB[0][lkq*4+i][lrow + 32] = to_tf32(tb1[i]);
        }
    }
    __syncthreads();

    int buf = 0;
    for (int kt = 0; kt < 256; kt++) {
        if (kt < 255) {
            int kg = (kt + 1) * 16 + lkq * 4;
            const float* srcA = (kg < 2048) ? (x + kg) : (hi + kg - 2048);
            va0 = *(const float4*)(srcA + (size_t)(tm0 + lrow)      * 2048);
            va1 = *(const float4*)(srcA + (size_t)(tm0 + lrow + 32) * 2048);
            vb0 = *(const float4*)(W_ih + (size_t)(rn0 + lrow)      * IN5 + kg);
            vb1 = *(const float4*)(W_ih + (size_t)(rn0 + lrow + 32) * IN5 + kg);
        }

        #pragma unroll
        for (int kk = 0; kk < 16; kk += 8) {
            uint32_t af[2][4], bf[4][2];
            #pragma unroll
            for (int mi = 0; mi < 2; mi++) {
                int rb = wm * 32 + mi * 16;
                af[mi][0] = __float_as_uint(sA[buf][kk + q    ][rb + grp    ]);
                af[mi][1] = __float_as_uint(sA[buf][kk + q    ][rb + grp + 8]);
                af[mi][2] = __float_as_uint(sA[buf][kk + q + 4][rb + grp    ]);
                af[mi][3] = __float_as_uint(sA[buf][kk + q + 4][rb + grp + 8]);
            }
            #pragma unroll
            for (int ni = 0; ni < 4; ni++) {
                int nb = wn * 32 + ni * 8;
                bf[ni][0] = __float_as_uint(sB[buf][kk + q    ][nb + grp]);
                bf[ni][1] = __float_as_uint(sB[buf][kk + q + 4][nb + grp]);
            }
            #pragma unroll
            for (int mi = 0; mi < 2; mi++)
                #pragma unroll
                for (int ni = 0; ni < 4; ni++)
                    mma_tf32(acc[mi][ni], af[mi], bf[ni]);
        }

        if (kt < 255) {
            float ta0[4] = {va0.x, va0.y, va0.z, va0.w};
            float ta1[4] = {va1.x, va1.y, va1.z, va1.w};
            float tb0[4] = {vb0.x, vb0.y, vb0.z, vb0.w};
            float tb1[4] = {vb1.x, vb1.y, vb1.z, vb1.w};
            int nb = buf ^ 1;
            #pragma unroll
            for (int i = 0; i < 4; i++) {
                sA[nb][lkq*4+i][lrow]      = to_tf32(ta0[i]);
                sA[nb][lkq*4+i][lrow + 32] = to_tf32(ta1[i]);
                sB[nb][lkq*4+i][lrow]      = to_tf32(tb0[i]);
                sB[nb][lkq*4+i][lrow + 32] = to_tf32(tb1[i]);
            }
        }
        __syncthreads();
        buf ^= 1;
    }

    // epilogue: add combined bias, write G row-major [512][4096]
    #pragma unroll
    for (int mi = 0; mi < 2; mi++)
        #pragma unroll
        for (int ni = 0; ni < 4; ni++) {
            int r0 = tm0 + wm * 32 + mi * 16 + grp;
            int c0 = rn0 + wn * 32 + ni * 8 + 2 * q;
            float bia0 = b_ih[c0]     + b_hh[c0];
            float bia1 = b_ih[c0 + 1] + b_hh[c0 + 1];
            g_G[(size_t)r0 * G4 + c0]           = acc[mi][ni][0] + bia0;
            g_G[(size_t)r0 * G4 + c0 + 1]       = acc[mi][ni][1] + bia1;
            g_G[(size_t)(r0 + 8) * G4 + c0]     = acc[mi][ni][2] + bia0;
            g_G[(size_t)(r0 + 8) * G4 + c0 + 1] = acc[mi][ni][3] + bia1;
        }
}

// ---------------- Phase 2: persistent recurrence ----------------
// 128 CTAs x 512 threads. CTA b owns h-indices j in [8b, 8b+8) => 32 gate rows
// {g*1024 + j}. W_r = W_ih[:,4096:] + W_hh held ENTIRELY in registers (64 fp32/thread).
// Warp w covers k in [64w, 64w+64); lane l covers local row l.
__global__ void __launch_bounds__(512, 1) recur_kernel(
    const float* __restrict__ W_ih, const float* __restrict__ W_hh)
{
    __shared__ float sh_h[HD];
    __shared__ float sh_part[16][32];

    const int tid  = threadIdx.x;
    const int w    = tid >> 5, l = tid & 31;
    const int gate = l >> 3, jl = l & 7;
    const int j    = blockIdx.x * 8 + jl;
    const int rg   = gate * HD + j;          // global gate row for this lane
    const int kb   = w * 64;

    // one-time: fuse recurrent weights into registers (fp32, exact)
    float wt[64];
    #pragma unroll
    for (int i = 0; i < 16; i++) {
        float4 a = *(const float4*)(W_ih + (size_t)rg * IN5 + G4 + kb + 4 * i);
        float4 b = *(const float4*)(W_hh + (size_t)rg * HD + kb + 4 * i);
        wt[4*i+0] = a.x + b.x;  wt[4*i+1] = a.y + b.y;
        wt[4*i+2] = a.z + b.z;  wt[4*i+3] = a.w + b.w;
    }

    float c = 0.f;
    unsigned target = 0;

    for (int t = 0; t < LSEQ; t++) {
        // stage h_{t-1} (L2-fresh) into smem
        const float* hb = g_h[t & 1];
        float2 hv2 = __ldcg((const float2*)(hb + 2 * tid));
        sh_h[2 * tid]     = hv2.x;
        sh_h[2 * tid + 1] = hv2.y;
        __syncthreads();

        float gpre = 0.f;
        if (tid < 32) gpre = g_G[(size_t)t * G4 + rg];   // overlaps with dot below

        float acc = 0.f;
        const float4* h4 = (const float4*)(sh_h + kb);   // broadcast reads
        #pragma unroll
        for (int i = 0; i < 16; i++) {
            float4 hh = h4[i];
            acc += wt[4*i+0]*hh.x + wt[4*i+1]*hh.y + wt[4*i+2]*hh.z + wt[4*i+3]*hh.w;
        }
        sh_part[w][l] = acc;
        __syncthreads();

        if (tid < 32) {
            float s = gpre;
            #pragma unroll
            for (int p = 0; p < 16; p++) s += sh_part[p][l];
            // lane l holds gate(l>>3) for j_local (l&7); gather i,f,g,o
            float iv = __shfl_sync(0xffffffffu, s, jl);
            float fv = __shfl_sync(0xffffffffu, s, jl + 8);
            float gv = __shfl_sync(0xffffffffu, s, jl + 16);
            float ov = __shfl_sync(0xffffffffu, s, jl + 24);
            if (l < 8) {
                float ig = 1.f / (1.f + expf(-iv));
                float fg = 1.f / (1.f + expf(-fv));
                float og = 1.f / (1.f + expf(-ov));
                c = fg * c + ig * tanhf(gv);
                float hn = og * tanhf(c);
                g_h[(t + 1) & 1][j] = hn;
                g_outs[(size_t)t * HD + j] = hn;
                __threadfence();
            }
        }
        __syncthreads();

        // grid barrier: release arrive + acquire spin
        target += NCTA;
        if (tid == 0) {
            asm volatile("red.release.gpu.global.add.u32 [%0], %1;"
                         :: "l"(&g_cnt), "r"(1u) : "memory");
            unsigned v;
            do {
                asm volatile("ld.acquire.gpu.global.u32 %0, [%1];"
                             : "=r"(v) : "l"(&g_cnt) : "memory");
            } while (v < target);
        }
        __syncthreads();
    }
}

// ---------------- Phase 3: out = outs @ W_fc^T + b_fc ----------------
__global__ void __launch_bounds__(128) fc_kernel(
    const float* __restrict__ W_fc, const float* __restrict__ b_fc,
    float* __restrict__ out)
{
    __shared__ float sh[HD];
    const int t = blockIdx.x;
    for (int i = threadIdx.x; i < HD; i += 128)
        sh[i] = g_outs[(size_t)t * HD + i];
    __syncthreads();

    const int n = threadIdx.x;
    if (n < LAB) {
        float acc = b_fc[n];
        const float4* wf = (const float4*)(W_fc + (size_t)n * HD);
        #pragma unroll 8
        for (int i = 0; i < HD / 4; i++) {
            float4 wv = wf[i];
            float4 hv = *(const float4*)(sh + 4 * i);
            acc += wv.x*hv.x + wv.y*hv.y + wv.z*hv.z + wv.w*hv.w;
        }
        out[(size_t)t * LAB + n] = acc;
    }
}

// ---------------- launch ----------------
extern "C" void kernel_launch(void* const* d_in, const int* in_sizes, int n_in,
                              void* d_out, int out_size)
{
    const float* x    = (const float*)d_in[0];
    const float* hi   = (const float*)d_in[1];
    const float* W_ih = (const float*)d_in[2];
    const float* W_hh = (const float*)d_in[3];
    const float* b_ih = (const float*)d_in[4];
    const float* b_hh = (const float*)d_in[5];
    const float* W_fc = (const float*)d_in[6];
    const float* b_fc = (const float*)d_in[7];
    float* out = (float*)d_out;

    reset_kernel<<<8, 256>>>();
    gemm_kernel<<<dim3(G4 / 64, LSEQ / 64), 128>>>(x, hi, W_ih, b_ih, b_hh);
    recur_kernel<<<NCTA, 512>>>(W_ih, W_hh);
    fc_kernel<<<LSEQ, 128>>>(W_fc, b_fc, out);
}